// round 12
// baseline (speedup 1.0000x reference)
#include <cuda_runtime.h>

#define BB 4096
#define FF 256
#define TT 128
#define DD 6
#define UU 16
#define NBIN 64

#define ROWS 32           /* batch rows per CTA (1 per thread-lane) */
#define LANES 8           /* trees per CTA = warps per CTA */
#define THREADS 256
#define TSPLIT 16
#define TPB (TT / TSPLIT) /* 8 trees per block, one group */
#define XSTRIDE 260       /* 256+4 pad: conflict-free LDS.128 across rows */
#define REDSTR 17         /* padded stride: lane*17 spans all banks */

typedef unsigned long long u64t;

// ---- packed f32x2 helpers (sm_103a FFMA2 path, PTX-only per SASS_QUICKREF) ----
__device__ __forceinline__ u64t ffma2(u64t a, u64t b, u64t c) {
    u64t d;
    asm("fma.rn.f32x2 %0, %1, %2, %3;" : "=l"(d) : "l"(a), "l"(b), "l"(c));
    return d;
}
__device__ __forceinline__ u64t fmul2(u64t a, u64t b) {
    u64t d;
    asm("mul.rn.f32x2 %0, %1, %2;" : "=l"(d) : "l"(a), "l"(b));
    return d;
}
__device__ __forceinline__ u64t pk2(float lo, float hi) {
    u64t p;
    asm("mov.b64 %0, {%1, %2};" : "=l"(p) : "f"(lo), "f"(hi));
    return p;
}
__device__ __forceinline__ float2 unpk2(u64t p) {
    float2 v;
    asm("mov.b64 {%0, %1}, %2;" : "=f"(v.x), "=f"(v.y) : "l"(p));
    return v;
}

// Scratch (device globals: no runtime allocation allowed)
__device__ __align__(16) float g_selW[TT * DD * FF];   // [t][d][f], sparsemax-ed selectors
__device__ __align__(16) float g_a[TT * DD];           // 0.5*exp(-lt)
__device__ __align__(16) float g_b[TT * DD];           // 0.5 - th*a

// ---------------------------------------------------------------------------
// Prep: sparsemax over D=6 per (f,t); also the per-(t,d) affine for sparsemoid
// ---------------------------------------------------------------------------
__global__ void prep_kernel(const float* __restrict__ fsl,
                            const float* __restrict__ th,
                            const float* __restrict__ lt)
{
    int n = blockIdx.x * blockDim.x + threadIdx.x;

    if (n < TT * DD) {
        float a = 0.5f * expf(-lt[n]);
        g_a[n] = a;
        g_b[n] = 0.5f - th[n] * a;
    }
    if (n >= FF * TT) return;

    int f = n / TT;
    int t = n - f * TT;

    const float* zp = fsl + (size_t)f * (TT * DD) + t * DD;
    float z[DD], zs[DD];
#pragma unroll
    for (int d = 0; d < DD; ++d) { z[d] = zp[d]; zs[d] = z[d]; }

    // descending bubble sorting network (15 comparators, D=6)
#pragma unroll
    for (int p = 0; p < DD - 1; ++p) {
#pragma unroll
        for (int i = 0; i < DD - 1 - p; ++i) {
            float mx = fmaxf(zs[i], zs[i + 1]);
            float mn = fminf(zs[i], zs[i + 1]);
            zs[i] = mx; zs[i + 1] = mn;
        }
    }

    // sparsemax threshold
    float cs = 0.f, css = 0.f;
    int kz = 0;
#pragma unroll
    for (int k = 1; k <= DD; ++k) {
        cs += zs[k - 1];
        if (1.0f + (float)k * zs[k - 1] > cs) { kz = k; css = cs; }
    }
    float tau = (css - 1.0f) / (float)kz;

#pragma unroll
    for (int d = 0; d < DD; ++d)
        g_selW[(size_t)(t * DD + d) * FF + f] = fmaxf(z[d] - tau, 0.0f);
}

// ---------------------------------------------------------------------------
// Fused main kernel. warp <-> tree, lane <-> single row. Everything hot is
// short-latency: x + sel in smem (29cyc), resp alone in L1D (39cyc).
// 2 CTAs/SM (smem 84.6KB, regs ~90 under the 128 cap -> no spills).
// ---------------------------------------------------------------------------
__global__ void __launch_bounds__(THREADS, 2)
main_kernel(const float* __restrict__ x,
            const float* __restrict__ resp,
            float* __restrict__ out)
{
    extern __shared__ float sm[];
    float* xs  = sm;                         // ROWS*XSTRIDE   (8320 f)
    float* sel = xs + ROWS * XSTRIDE;        // LANES*DD*FF    (12288 f)
    float* red = sel + LANES * DD * FF;      // ROWS*REDSTR    (544 f)

    const int tid  = threadIdx.x;
    const int lane = tid & 31;
    const int wid  = tid >> 5;               // warp -> tree
    const int b0   = blockIdx.x * ROWS;
    const int t0   = blockIdx.y * TPB;
    const int t    = t0 + wid;

    // stage x tile (coalesced gmem -> padded smem), 32 rows
    for (int i = tid; i < ROWS * (FF / 4); i += THREADS) {
        int r = i >> 6, c4 = i & 63;
        float4 v = reinterpret_cast<const float4*>(x + (size_t)(b0 + r) * FF)[c4];
        *reinterpret_cast<float4*>(xs + r * XSTRIDE + 4 * c4) = v;
    }
    // stage selectors for this block's 8 trees (contiguous slab)
    {
        const float4* ssrc = reinterpret_cast<const float4*>(
            g_selW + (size_t)t0 * DD * FF);
        float4* sdst = reinterpret_cast<float4*>(sel);
        for (int i = tid; i < LANES * DD * FF / 4; i += THREADS) sdst[i] = ssrc[i];
    }
    // zero reduction slab
    for (int i = tid; i < ROWS * REDSTR; i += THREADS) red[i] = 0.f;

    // per-tree sparsemoid affine (uniform loads, register-resident)
    float ra[DD], rb[DD];
#pragma unroll
    for (int d = 0; d < DD; ++d) {
        ra[d] = __ldg(g_a + t * DD + d);
        rb[d] = __ldg(g_b + t * DD + d);
    }
    __syncthreads();

    const ulonglong2* selT =
        reinterpret_cast<const ulonglong2*>(sel + wid * DD * FF);
    const ulonglong2* xr =
        reinterpret_cast<const ulonglong2*>(xs + lane * XSTRIDE);

    // fv[d] = x_row . sel[d] : 12 packed FMA chains, all-smem operands
    u64t pa[DD], pb[DD];
#pragma unroll
    for (int d = 0; d < DD; ++d) { pa[d] = 0ULL; pb[d] = 0ULL; }
#pragma unroll 8
    for (int k4 = 0; k4 < FF / 4; ++k4) {
        ulonglong2 xv = xr[k4];
#pragma unroll
        for (int d = 0; d < DD; ++d) {
            ulonglong2 sv = selT[d * (FF / 4) + k4];   // broadcast LDS.128
            pa[d] = ffma2(xv.x, sv.x, pa[d]);
            pb[d] = ffma2(xv.y, sv.y, pb[d]);
        }
    }

    // sparsemoid
    float s[DD];
#pragma unroll
    for (int d = 0; d < DD; ++d) {
        float2 va = unpk2(pa[d]), vb = unpk2(pb[d]);
        s[d] = __saturatef(((va.x + va.y) + (vb.x + vb.y)) * ra[d] + rb[d]);
    }

    // shared subtree over bits 1..3 (8 entries); bits 4,5 per-quarter scalar,
    // bit 0 the packed pair.
    float v8[8];
    v8[0] = s[1];  v8[1] = 1.0f - s[1];
#pragma unroll
    for (int d = 2; d < 4; ++d) {
#pragma unroll
        for (int c = 0; c < (1 << (d - 1)); ++c) {
            float lo = v8[c];
            v8[c] = lo * s[d];
            v8[c + (1 << (d - 1))] = lo * (1.0f - s[d]);
        }
    }

    const ulonglong2* rbase =
        reinterpret_cast<const ulonglong2*>(resp + (size_t)t * UU * NBIN);

    // register accumulators across the 4 bin-quarters
    float acc[UU];
#pragma unroll
    for (int u = 0; u < UU; ++u) acc[u] = 0.f;

    // quarters over bins: h bit0 <-> s[4], h bit1 <-> s[5]
#pragma unroll
    for (int h = 0; h < 4; ++h) {
        float q = ((h & 1) ? (1.0f - s[4]) : s[4]) *
                  ((h & 2) ? (1.0f - s[5]) : s[5]);
        const u64t qs = pk2(q * s[0], q * (1.0f - s[0]));

        u64t w[8];
#pragma unroll
        for (int j = 0; j < 8; ++j)
            w[j] = fmul2(pk2(v8[j], v8[j]), qs);

#pragma unroll
        for (int u = 0; u < UU; ++u) {
            const ulonglong2* rr = rbase + u * (NBIN / 4) + 4 * h;
            u64t c0 = 0ULL, c1 = 0ULL;
#pragma unroll
            for (int qq = 0; qq < 4; ++qq) {
                ulonglong2 rv = __ldg(rr + qq);   // uniform, L1-resident
                c0 = ffma2(w[2 * qq + 0], rv.x, c0);
                c1 = ffma2(w[2 * qq + 1], rv.y, c1);
            }
            float2 a0 = unpk2(c0), a1 = unpk2(c1);
            acc[u] += (a0.x + a0.y) + (a1.x + a1.y);
        }
    }

    // flush: shared atomics, stride-17 slab (conflict-free lane spread)
#pragma unroll
    for (int u = 0; u < UU; ++u)
        atomicAdd(&red[lane * REDSTR + u], acc[u]);
    __syncthreads();

    // CTA result -> global atomic accumulation (tree-split across y)
    for (int i = tid; i < ROWS * UU; i += THREADS) {
        int r = i >> 4, u = i & 15;
        atomicAdd(&out[(size_t)(b0 + r) * UU + u], red[r * REDSTR + u]);
    }
}

// ---------------------------------------------------------------------------
extern "C" void kernel_launch(void* const* d_in, const int* in_sizes, int n_in,
                              void* d_out, int out_size)
{
    const float* x    = (const float*)d_in[0];
    const float* fsl  = (const float*)d_in[1];
    const float* th   = (const float*)d_in[2];
    const float* lt   = (const float*)d_in[3];
    const float* resp = (const float*)d_in[4];
    float* out = (float*)d_out;

    cudaMemsetAsync(out, 0, (size_t)out_size * sizeof(float));

    prep_kernel<<<(FF * TT + 255) / 256, 256>>>(fsl, th, lt);

    const int smem = (ROWS * XSTRIDE + LANES * DD * FF + ROWS * REDSTR)
                     * (int)sizeof(float);
    cudaFuncSetAttribute(main_kernel, cudaFuncAttributeMaxDynamicSharedMemorySize, smem);
    main_kernel<<<dim3(BB / ROWS, TSPLIT), THREADS, smem>>>(x, resp, out);
}